// round 13
// baseline (speedup 1.0000x reference)
#include <cuda_runtime.h>
#include <cstdint>

// LatticeSnake: B=32, L=512, W=9. Output [B, L, 9,9,9, 1] fp32 (48 MB).
// Doubled walk coords (the 2(L-1) grid offset cancels):
//   residue j:   p = 2*idx[j],         v = acids[j]*mask[j]
//   midpoint k:  p = idx[k]+idx[k+1],  v = (acids[k]+acids[k+1]+1)*mask[k+1]
//   voxel (i,r): value = sum of points at p == 2*idx[i] + r - 4
//
// R13 = R12 with:
//   - points packed short4 (8B, LDG.64) + separate value array read only on
//     bbox hit: scan L2 traffic 32MB -> 16MB
//   - K2 __launch_bounds__(128,12): 42-reg budget (kill potential spills)
//   - K1 parallelized 4x: 128 CTAs x 128 thr, quarter-batch each

#define LS_L    512
#define LS_W    9
#define LS_W3   729
#define LS_R    8                // windows per K2 CTA
#define LS_NT   128
#define LS_NG   (LS_L / LS_R)    // 64 groups per batch
#define LS_MP   1024             // padded point count per batch
#define GRID_F  2560             // >= worst-case vol 15*13*13 = 2535

__device__ short4 g_pts[64 * LS_MP];         // packed snake point coords
__device__ float  g_val[64 * LS_MP];         // snake point values
__device__ int    g_meta[64 * LS_NG * 16];   // per group: bbox(6) + base[8]

// ---------------- Kernel 1: points + per-group meta ----------------
// grid = 4*B CTAs; CTA handles one quarter-batch (128 residues/midpoints,
// 16 groups of meta). Needs coords[r0 .. r0+128] (129 when not last quarter).
__global__ __launch_bounds__(128)
void ls_prep_kernel(const float* __restrict__ acids,
                    const float* __restrict__ mask,
                    const int*   __restrict__ idx)
{
    __shared__ int   sidx[129 * 3];
    __shared__ float sA[129];
    __shared__ float sM[129];

    const int b   = blockIdx.x >> 2;
    const int q   = blockIdx.x & 3;
    const int r0  = q * 128;
    const int tid = threadIdx.x;

    const int*   gi = idx   + ((size_t)b * LS_L + r0) * 3;
    const float* ga = acids + (size_t)b * LS_L + r0;
    const float* gm = mask  + (size_t)b * LS_L + r0;

    const int nC = (q < 3) ? 129 : 128;      // entries to stage
    for (int e = tid; e < nC * 3; e += 128) sidx[e] = gi[e];
    for (int e = tid; e < nC;     e += 128) { sA[e] = ga[e]; sM[e] = gm[e]; }
    __syncthreads();

    const int jj = 3 * tid;

    // residue point
    g_pts[b * LS_MP + r0 + tid] =
        make_short4((short)(2 * sidx[jj + 0]), (short)(2 * sidx[jj + 1]),
                    (short)(2 * sidx[jj + 2]), 0);
    g_val[b * LS_MP + r0 + tid] = sA[tid] * sM[tid];

    // midpoint (last thread of last quarter writes the sentinel @ slot 1023)
    const int mi = b * LS_MP + LS_L + r0 + tid;
    if (q < 3 || tid < 127) {
        g_pts[mi] = make_short4((short)(sidx[jj + 0] + sidx[jj + 3]),
                                (short)(sidx[jj + 1] + sidx[jj + 4]),
                                (short)(sidx[jj + 2] + sidx[jj + 5]), 0);
        g_val[mi] = (sA[tid] + sA[tid + 1] + 1.0f) * sM[tid + 1];
    } else {
        g_pts[mi] = make_short4(16384, 16384, 16384, 0);   // sentinel
        g_val[mi] = 0.0f;
    }

    // meta: 128 threads = 16 groups x 8 windows
    {
        const int gl  = tid >> 3;            // local group 0..15
        const int r   = tid & 7;
        const int cjj = 3 * (gl * 8 + r);    // window center within quarter
        const int cx = 2 * sidx[cjj + 0];
        const int cy = 2 * sidx[cjj + 1];
        const int cz = 2 * sidx[cjj + 2];
        int xmin = cx, xmax = cx, ymin = cy, ymax = cy, zmin = cz, zmax = cz;
        #pragma unroll
        for (int d = 4; d >= 1; d >>= 1) {   // segmented reduce over 8 lanes
            xmin = min(xmin, __shfl_xor_sync(0xffffffffu, xmin, d));
            xmax = max(xmax, __shfl_xor_sync(0xffffffffu, xmax, d));
            ymin = min(ymin, __shfl_xor_sync(0xffffffffu, ymin, d));
            ymax = max(ymax, __shfl_xor_sync(0xffffffffu, ymax, d));
            zmin = min(zmin, __shfl_xor_sync(0xffffffffu, zmin, d));
            zmax = max(zmax, __shfl_xor_sync(0xffffffffu, zmax, d));
        }
        const int syv = ymax - ymin + 9;
        const int szv = zmax - zmin + 9;
        int* m = g_meta + (b * LS_NG + q * 16 + gl) * 16;
        m[6 + r] = ((cx - xmin) * syv + (cy - ymin)) * szv + (cz - zmin);
        if (r == 0) {
            m[0] = xmin - 4; m[1] = ymin - 4; m[2] = zmin - 4;
            m[3] = xmax - xmin + 9; m[4] = syv; m[5] = szv;
        }
    }
}

// ---------------- Kernel 2: main (grid gather) ----------------
__global__ __launch_bounds__(LS_NT, 12)
void lattice_snake_kernel(float* __restrict__ out)
{
    __shared__ alignas(16) float grid[GRID_F];   // 10240 B
    __shared__ int sMeta[16];                    // bbox(6) + base[8]

    const int b   = blockIdx.x >> 6;            // / LS_NG
    const int g   = blockIdx.x & (LS_NG - 1);
    const int tid = threadIdx.x;

    const short4* gp = g_pts + b * LS_MP;
    const float*  gv = g_val + b * LS_MP;
    float* gout = out + (size_t)(b * LS_L + g * LS_R) * LS_W3;

    // meta load (overlaps zeroing)
    if (tid < 14) sMeta[tid] = g_meta[(b * LS_NG + g) * 16 + tid];

    // ---- zero grid (640 float4) ----
    {
        float4* g4 = reinterpret_cast<float4*>(grid);
        const float4 z = make_float4(0.f, 0.f, 0.f, 0.f);
        #pragma unroll
        for (int e = tid; e < GRID_F / 4; e += LS_NT) g4[e] = z;
    }
    __syncthreads();

    const int gxl = sMeta[0], gyl = sMeta[1], gzl = sMeta[2];
    const int sx  = sMeta[3], sy  = sMeta[4], sz  = sMeta[5];

    // ---- scan 1024 packed points; 8 coalesced LDG.64 rounds (MLP 8) ----
    #pragma unroll
    for (int rnd = 0; rnd < LS_MP / LS_NT; rnd++) {
        const int i = rnd * LS_NT + tid;
        const short4 p = gp[i];
        const unsigned ux = (unsigned)((int)p.x - gxl);
        const unsigned uy = (unsigned)((int)p.y - gyl);
        const unsigned uz = (unsigned)((int)p.z - gzl);
        if (ux < (unsigned)sx && uy < (unsigned)sy && uz < (unsigned)sz)
            atomicAdd(&grid[(ux * sy + uy) * sz + uz], gv[i]);  // rare
    }

    // per-thread voxel decomposition (6 rounds of 128 cover 729)
    int ro[6];
    #pragma unroll
    for (int k = 0; k < 6; k++) {
        const int lin = tid + k * LS_NT;
        const int rx  = lin / 81;
        const int rem = lin - rx * 81;
        const int ry  = rem / 9;
        const int rz  = rem - ry * 9;
        ro[k] = (rx * sy + ry) * sz + rz;
    }
    __syncthreads();   // grid complete

    // ---- gather: voxel = one LDS + one coalesced STG.32 ----
    const bool k5ok = tid < (LS_W3 - 5 * LS_NT);   // 89
    #pragma unroll
    for (int w = 0; w < LS_R; w++) {
        const int Aw = sMeta[6 + w];               // broadcast LDS
        float* gw = gout + w * LS_W3;
        gw[tid]              = grid[Aw + ro[0]];
        gw[tid + 1 * LS_NT]  = grid[Aw + ro[1]];
        gw[tid + 2 * LS_NT]  = grid[Aw + ro[2]];
        gw[tid + 3 * LS_NT]  = grid[Aw + ro[3]];
        gw[tid + 4 * LS_NT]  = grid[Aw + ro[4]];
        if (k5ok) gw[tid + 5 * LS_NT] = grid[Aw + ro[5]];
    }
}

extern "C" void kernel_launch(void* const* d_in, const int* in_sizes, int n_in,
                              void* d_out, int out_size)
{
    const float* acids = (const float*)d_in[0];   // [B, L]
    const float* mask  = (const float*)d_in[1];   // [B, L]
    const int*   idx   = (const int*)  d_in[2];   // [B, L, 3]
    float*       out   = (float*)d_out;           // [B, L, 9,9,9, 1]

    const int nB = in_sizes[0] / LS_L;            // 32
    ls_prep_kernel<<<nB * 4, 128>>>(acids, mask, idx);
    lattice_snake_kernel<<<nB * LS_NG, LS_NT>>>(out);
}